// round 2
// baseline (speedup 1.0000x reference)
#include <cuda_runtime.h>
#include <cstdint>
#include <cstddef>

// Problem constants
#define Bc   2
#define Tc   8
#define Nc   4000
#define Ec   40000
#define FIN0 32
#define Hc   4
#define Cc   64
#define HLc  128
#define FHc  128
#define BTc  (Bc * Tc)
#define EPc  (Ec + Nc)      // edges + self loops
#define HCc  (Hc * Cc)      // 256

// ---------------- scratch (device globals; no allocations allowed) ----------
__device__ float    g_hbuf [(size_t)BTc * Nc * HCc];   // per-layer h = x@W   [BT,N,H*C]
__device__ float    g_als  [BTc * Nc * Hc];            // src attention logits [BT,N,H]
__device__ float    g_ald  [BTc * Nc * Hc];            // dst attention logits
__device__ float    g_g1   [(size_t)BTc * Nc * Cc];    // layer1 out
__device__ float    g_g2   [(size_t)BTc * Nc * Cc];    // layer2 out
__device__ float    g_WihT [Cc * 4 * HLc];             // [64,512]
__device__ float    g_WhhT [HLc * 4 * HLc];            // [128,512]
// CSR (graph identical across all BT instances)
__device__ int      g_cnt [Nc];
__device__ int      g_cur [Nc];
__device__ int      g_row [Nc + 1];
__device__ int      g_esrc[EPc];

// ---------------- helpers ----------------------------------------------------
__device__ __forceinline__ float fsig(float x) { return 1.f / (1.f + __expf(-x)); }
__device__ __forceinline__ float ftanh(float x) {
    x = fminf(fmaxf(x, -15.f), 15.f);
    float e = __expf(2.f * x);
    return (e - 1.f) / (e + 1.f);
}

// ---------------- CSR build ---------------------------------------------------
__global__ void csr_zero()
{
    int i = blockIdx.x * blockDim.x + threadIdx.x;
    if (i < Nc) g_cnt[i] = 0;
}

__global__ void csr_count(const int* __restrict__ ei)
{
    int e = blockIdx.x * blockDim.x + threadIdx.x;
    if (e >= EPc) return;
    int d = (e < Ec) ? ei[Ec + e] : (e - Ec);
    atomicAdd(&g_cnt[d], 1);
}

// single-block exclusive scan over g_cnt -> g_row; also zeros cursors
__global__ void __launch_bounds__(1024) csr_scan()
{
    __shared__ int s0[1024], s1[1024];
    int t = threadIdx.x;
    int base = t * 4;
    int v[4];
    int sum = 0;
#pragma unroll
    for (int k = 0; k < 4; ++k) {
        int idx = base + k;
        int c = (idx < Nc) ? g_cnt[idx] : 0;
        v[k] = sum; sum += c;
    }
    s0[t] = sum;
    __syncthreads();
    int* src = s0; int* dst = s1;
    for (int off = 1; off < 1024; off <<= 1) {
        int val = src[t];
        if (t >= off) val += src[t - off];
        dst[t] = val;
        __syncthreads();
        int* tmp = src; src = dst; dst = tmp;
    }
    int excl = (t > 0) ? src[t - 1] : 0;
#pragma unroll
    for (int k = 0; k < 4; ++k) {
        int idx = base + k;
        if (idx < Nc) { g_row[idx] = excl + v[k]; g_cur[idx] = 0; }
    }
    if (t == 0) g_row[Nc] = src[1023];
}

__global__ void csr_scatter(const int* __restrict__ ei)
{
    int e = blockIdx.x * blockDim.x + threadIdx.x;
    if (e >= EPc) return;
    int s, d;
    if (e < Ec) { s = ei[e]; d = ei[Ec + e]; } else { s = e - Ec; d = s; }
    int pos = atomicAdd(&g_cur[d], 1);
    g_esrc[g_row[d] + pos] = s;
}

// ---------------- GAT: node projection + attention logits --------------------
// One block per (bt,node): h = x@W [256 ch], a_src/a_dst head reductions.
template <int FIN>
__global__ void gat_node_proj(const float* __restrict__ x, const float* __restrict__ W,
                              const float* __restrict__ a_src, const float* __restrict__ a_dst)
{
    int inst = blockIdx.x;              // bt*N + n
    int t = threadIdx.x;                // 0..255 (h*64+c)
    __shared__ float xs[FIN];
    __shared__ float sred[16];
    if (t < FIN) xs[t] = x[(size_t)inst * FIN + t];
    __syncthreads();
    float acc = 0.f;
#pragma unroll
    for (int k = 0; k < FIN; ++k) acc = fmaf(xs[k], W[k * HCc + t], acc);
    g_hbuf[(size_t)inst * HCc + t] = acc;
    float sv = acc * a_src[t];
    float dv = acc * a_dst[t];
#pragma unroll
    for (int off = 16; off > 0; off >>= 1) {
        sv += __shfl_down_sync(0xffffffffu, sv, off);
        dv += __shfl_down_sync(0xffffffffu, dv, off);
    }
    int w = t >> 5;
    if ((t & 31) == 0) { sred[w] = sv; sred[8 + w] = dv; }
    __syncthreads();
    if (t < Hc) {
        g_als[inst * Hc + t] = sred[2 * t] + sred[2 * t + 1];
        g_ald[inst * Hc + t] = sred[8 + 2 * t] + sred[8 + 2 * t + 1];
    }
}

// ---------------- GAT: atomic-free gather over incoming edges ----------------
// Block = (dst, bt), 64 threads. Thread t owns channels [4t, 4t+4) (head t>>4).
// Pass A: segment max per head. Pass B: exp + register accumulate + denom.
// Epilogue: divide, head-mean, bias, relu, store.
__global__ void __launch_bounds__(64) gat_gather(const float* __restrict__ b,
                                                 float* __restrict__ out)
{
    int d  = blockIdx.x;
    int bt = blockIdx.y;
    int t  = threadIdx.x;               // 0..63
    int j  = t & 3;                     // head lane for logit work
    int head = t >> 4;                  // head for channel ownership
    int beg = g_row[d], deg = g_row[d + 1] - beg;
    float aldv = g_ald[(bt * Nc + d) * Hc + j];

    __shared__ float sm[8], sdenom[8], se[64], sacc[HCc];
    __shared__ int   ssrc[16];

    // pass A: max over incoming edges, per head
    float lm = -1e30f;
    for (int i0 = 0; i0 < deg; i0 += 16) {
        int i = i0 + (t >> 2);
        if (i < deg) {
            int s = g_esrc[beg + i];
            float v = g_als[(bt * Nc + s) * Hc + j] + aldv;
            v = v > 0.f ? v : 0.2f * v;
            lm = fmaxf(lm, v);
        }
    }
#pragma unroll
    for (int off = 4; off < 32; off <<= 1)
        lm = fmaxf(lm, __shfl_xor_sync(0xffffffffu, lm, off));
    if ((t & 31) < 4) sm[(t >> 5) * 4 + j] = lm;
    __syncthreads();
    float mh = fmaxf(sm[j], sm[4 + j]);

    // pass B: exp, denom, channel accumulate
    float dsum = 0.f;
    float4 acc = make_float4(0.f, 0.f, 0.f, 0.f);
    for (int c0 = 0; c0 < deg; c0 += 16) {
        int nim = min(16, deg - c0);
        if (t < nim) ssrc[t] = g_esrc[beg + c0 + t];
        __syncthreads();
        int i = t >> 2;
        if (i < nim) {
            int s = ssrc[i];
            float v = g_als[(bt * Nc + s) * Hc + j] + aldv;
            v = v > 0.f ? v : 0.2f * v;
            float e = __expf(v - mh);
            se[t] = e;
            dsum += e;
        }
        __syncthreads();
        for (int i2 = 0; i2 < nim; ++i2) {
            int s = ssrc[i2];
            float e = se[i2 * 4 + head];
            const float4 h4 = *(const float4*)(g_hbuf + ((size_t)(bt * Nc + s)) * HCc + t * 4);
            acc.x = fmaf(e, h4.x, acc.x);
            acc.y = fmaf(e, h4.y, acc.y);
            acc.z = fmaf(e, h4.z, acc.z);
            acc.w = fmaf(e, h4.w, acc.w);
        }
        __syncthreads();                 // before reusing ssrc/se
    }
#pragma unroll
    for (int off = 4; off < 32; off <<= 1)
        dsum += __shfl_xor_sync(0xffffffffu, dsum, off);
    if ((t & 31) < 4) sdenom[(t >> 5) * 4 + j] = dsum;
    __syncthreads();
    float invden = 1.f / (sdenom[head] + sdenom[4 + head]);
    sacc[4 * t + 0] = acc.x * invden;
    sacc[4 * t + 1] = acc.y * invden;
    sacc[4 * t + 2] = acc.z * invden;
    sacc[4 * t + 3] = acc.w * invden;
    __syncthreads();
    if (t < 16) {                        // 16 threads x 4 channels = 64 out channels
        float4 o;
        float* op = (float*)&o;
#pragma unroll
        for (int k = 0; k < 4; ++k) {
            int c = 4 * t + k;
            float sv = sacc[c] + sacc[Cc + c] + sacc[2 * Cc + c] + sacc[3 * Cc + c];
            op[k] = fmaxf(0.25f * sv + b[c], 0.f);
        }
        *(float4*)(out + ((size_t)(bt * Nc + d)) * Cc + 4 * t) = o;
    }
}

// ---------------- LSTM weight transpose (coalesced gate access) ---------------
__global__ void transpose_weights(const float* __restrict__ Wih, const float* __restrict__ Whh)
{
    int idx = blockIdx.x * blockDim.x + threadIdx.x;
    if (idx < Cc * 4 * HLc)  { int k = idx >> 9, j = idx & 511; g_WihT[idx] = Wih[j * Cc  + k]; }
    if (idx < HLc * 4 * HLc) { int k = idx >> 9, j = idx & 511; g_WhhT[idx] = Whh[j * HLc + k]; }
}

// ---------------- fused LSTM (all 8 steps) + fusion head ----------------------
// Block = 16 batch elements, 128 threads (thread u = hidden unit u).
__global__ void __launch_bounds__(HLc) lstm_head(
    const float* __restrict__ b_ih, const float* __restrict__ b_hh,
    const float* __restrict__ Wf,   const float* __restrict__ bfv,
    const float* __restrict__ Wo,   const float* __restrict__ bov,
    float* __restrict__ out)
{
    const int TB = 16;
    int u   = threadIdx.x;
    int gb0 = blockIdx.x * TB;          // gb = b*N + n; 16 | N so b constant per block
    int b   = gb0 / Nc;
    int n0  = gb0 - b * Nc;
    __shared__ float xs[TB][Cc];
    __shared__ float hs[TB][HLc];
    __shared__ float red[TB][HLc];
    float creg[TB];
#pragma unroll
    for (int bb = 0; bb < TB; ++bb) { creg[bb] = 0.f; hs[bb][u] = 0.f; }
    float bi  = b_ih[u]           + b_hh[u];
    float bff = b_ih[HLc + u]     + b_hh[HLc + u];
    float bg  = b_ih[2 * HLc + u] + b_hh[2 * HLc + u];
    float bo  = b_ih[3 * HLc + u] + b_hh[3 * HLc + u];

    for (int t = 0; t < Tc; ++t) {
        const float* gsrc = g_g2 + ((size_t)(b * Tc + t) * Nc + n0) * Cc;
        __syncthreads();
        for (int i = u; i < TB * Cc; i += HLc) xs[0][i] = gsrc[i];   // contiguous 1024 f32
        __syncthreads();
        float ai[TB], af[TB], ag[TB], ao[TB];
#pragma unroll
        for (int bb = 0; bb < TB; ++bb) { ai[bb] = bi; af[bb] = bff; ag[bb] = bg; ao[bb] = bo; }
        for (int k = 0; k < Cc; ++k) {
            float wi = g_WihT[k * 512 + u];
            float wf = g_WihT[k * 512 + HLc + u];
            float wg = g_WihT[k * 512 + 2 * HLc + u];
            float wo = g_WihT[k * 512 + 3 * HLc + u];
#pragma unroll
            for (int bb = 0; bb < TB; ++bb) {
                float x = xs[bb][k];
                ai[bb] = fmaf(wi, x, ai[bb]);
                af[bb] = fmaf(wf, x, af[bb]);
                ag[bb] = fmaf(wg, x, ag[bb]);
                ao[bb] = fmaf(wo, x, ao[bb]);
            }
        }
        for (int k = 0; k < HLc; ++k) {
            float wi = g_WhhT[k * 512 + u];
            float wf = g_WhhT[k * 512 + HLc + u];
            float wg = g_WhhT[k * 512 + 2 * HLc + u];
            float wo = g_WhhT[k * 512 + 3 * HLc + u];
#pragma unroll
            for (int bb = 0; bb < TB; ++bb) {
                float h = hs[bb][k];
                ai[bb] = fmaf(wi, h, ai[bb]);
                af[bb] = fmaf(wf, h, af[bb]);
                ag[bb] = fmaf(wg, h, ag[bb]);
                ao[bb] = fmaf(wo, h, ao[bb]);
            }
        }
        __syncthreads();                 // all hs reads done before overwrite
#pragma unroll
        for (int bb = 0; bb < TB; ++bb) {
            float cv = fsig(af[bb]) * creg[bb] + fsig(ai[bb]) * ftanh(ag[bb]);
            creg[bb] = cv;
            hs[bb][u] = fsig(ao[bb]) * ftanh(cv);
        }
    }
    __syncthreads();
    // fusion head: xs still holds t=T-1 (= g_last); hs holds h_T
#pragma unroll 1
    for (int bb = 0; bb < TB; ++bb) {
        float f = bfv[u];
        for (int k = 0; k < HLc; ++k) f = fmaf(hs[bb][k], Wf[k * FHc + u], f);
        for (int k = 0; k < Cc;  ++k) f = fmaf(xs[bb][k], Wf[(HLc + k) * FHc + u], f);
        f = fmaxf(f, 0.f);
        red[bb][u] = f * Wo[u];
    }
    __syncthreads();
    if (u < TB) {
        float s = bov[0];
        for (int k = 0; k < HLc; ++k) s += red[u][k];
        out[gb0 + u] = s;
    }
}

// ---------------- launch ------------------------------------------------------
extern "C" void kernel_launch(void* const* d_in, const int* in_sizes, int n_in,
                              void* d_out, int out_size)
{
    const float* x_seq  = (const float*)d_in[0];
    const float* W1     = (const float*)d_in[1];
    const float* a_src1 = (const float*)d_in[2];
    const float* a_dst1 = (const float*)d_in[3];
    const float* b1     = (const float*)d_in[4];
    const float* W2     = (const float*)d_in[5];
    const float* a_src2 = (const float*)d_in[6];
    const float* a_dst2 = (const float*)d_in[7];
    const float* b2     = (const float*)d_in[8];
    const float* W_ih   = (const float*)d_in[9];
    const float* W_hh   = (const float*)d_in[10];
    const float* b_ih   = (const float*)d_in[11];
    const float* b_hh   = (const float*)d_in[12];
    const float* Wf     = (const float*)d_in[13];
    const float* bf     = (const float*)d_in[14];
    const float* Wo     = (const float*)d_in[15];
    const float* bo     = (const float*)d_in[16];
    const int*   ei     = (const int*)d_in[17];
    float* out = (float*)d_out;

    float* g1p; cudaGetSymbolAddress((void**)&g1p, g_g1);
    float* g2p; cudaGetSymbolAddress((void**)&g2p, g_g2);

    dim3 ggrid(Nc, BTc);

    // CSR build (graph shared across all BT instances)
    csr_zero<<<(Nc + 255) / 256, 256>>>();
    csr_count<<<(EPc + 255) / 256, 256>>>(ei);
    csr_scan<<<1, 1024>>>();
    csr_scatter<<<(EPc + 255) / 256, 256>>>(ei);

    // Layer 1
    gat_node_proj<FIN0><<<BTc * Nc, HCc>>>(x_seq, W1, a_src1, a_dst1);
    gat_gather<<<ggrid, 64>>>(b1, g1p);

    // Layer 2 (input = g1)
    gat_node_proj<Cc><<<BTc * Nc, HCc>>>(g1p, W2, a_src2, a_dst2);
    gat_gather<<<ggrid, 64>>>(b2, g2p);

    // LSTM + head
    transpose_weights<<<(HLc * 4 * HLc + 255) / 256, 256>>>(W_ih, W_hh);
    lstm_head<<<(Bc * Nc) / 16, HLc>>>(b_ih, b_hh, Wf, bf, Wo, bo, out);
}

// round 3
// speedup vs baseline: 1.2728x; 1.2728x over previous
#include <cuda_runtime.h>
#include <cstdint>
#include <cstddef>

// Problem constants
#define Bc   2
#define Tc   8
#define Nc   4000
#define Ec   40000
#define FIN0 32
#define Hc   4
#define Cc   64
#define HLc  128
#define FHc  128
#define BTc  (Bc * Tc)
#define EPc  (Ec + Nc)      // edges + self loops
#define HCc  (Hc * Cc)      // 256

typedef unsigned long long u64;

// ---------------- scratch (device globals; no allocations allowed) ----------
__device__ float    g_hbuf [(size_t)BTc * Nc * HCc];   // per-layer h = x@W   [BT,N,H*C]
__device__ float    g_als  [BTc * Nc * Hc];            // src attention logits [BT,N,H]
__device__ float    g_ald  [BTc * Nc * Hc];            // dst attention logits
__device__ float    g_g1   [(size_t)BTc * Nc * Cc];    // layer1 out
__device__ float    g_g2   [(size_t)BTc * Nc * Cc];    // layer2 out
__device__ float    g_WihT [Cc  * HLc * 4];            // [k][u][gate]
__device__ float    g_WhhT [HLc * HLc * 4];            // [k][u][gate]
// CSR (graph identical across all BT instances)
__device__ int      g_cnt [Nc];
__device__ int      g_cur [Nc];
__device__ int      g_row [Nc + 1];
__device__ int      g_esrc[EPc];

// ---------------- f32x2 helpers ----------------------------------------------
__device__ __forceinline__ u64 pk2(float lo, float hi) {
    u64 r; asm("mov.b64 %0, {%1, %2};" : "=l"(r) : "f"(lo), "f"(hi)); return r;
}
__device__ __forceinline__ void fma2(u64& d, u64 a, u64 b) {
    asm("fma.rn.f32x2 %0, %1, %2, %3;" : "=l"(d) : "l"(a), "l"(b), "l"(d));
}
__device__ __forceinline__ void upk2(float& lo, float& hi, u64 v) {
    asm("mov.b64 {%0, %1}, %2;" : "=f"(lo), "=f"(hi) : "l"(v));
}

// ---------------- math helpers ------------------------------------------------
__device__ __forceinline__ float fsig(float x) { return 1.f / (1.f + __expf(-x)); }
__device__ __forceinline__ float ftanh(float x) {
    x = fminf(fmaxf(x, -15.f), 15.f);
    float e = __expf(2.f * x);
    return (e - 1.f) / (e + 1.f);
}
__device__ __forceinline__ float wsum(float v) {
#pragma unroll
    for (int off = 16; off > 0; off >>= 1) v += __shfl_down_sync(0xffffffffu, v, off);
    return v;
}

// ---------------- CSR build ---------------------------------------------------
__global__ void csr_zero()
{
    int i = blockIdx.x * blockDim.x + threadIdx.x;
    if (i < Nc) g_cnt[i] = 0;
}

__global__ void csr_count(const int* __restrict__ ei)
{
    int e = blockIdx.x * blockDim.x + threadIdx.x;
    if (e >= EPc) return;
    int d = (e < Ec) ? ei[Ec + e] : (e - Ec);
    atomicAdd(&g_cnt[d], 1);
}

__global__ void __launch_bounds__(1024) csr_scan()
{
    __shared__ int s0[1024], s1[1024];
    int t = threadIdx.x;
    int base = t * 4;
    int v[4];
    int sum = 0;
#pragma unroll
    for (int k = 0; k < 4; ++k) {
        int idx = base + k;
        int c = (idx < Nc) ? g_cnt[idx] : 0;
        v[k] = sum; sum += c;
    }
    s0[t] = sum;
    __syncthreads();
    int* src = s0; int* dst = s1;
    for (int off = 1; off < 1024; off <<= 1) {
        int val = src[t];
        if (t >= off) val += src[t - off];
        dst[t] = val;
        __syncthreads();
        int* tmp = src; src = dst; dst = tmp;
    }
    int excl = (t > 0) ? src[t - 1] : 0;
#pragma unroll
    for (int k = 0; k < 4; ++k) {
        int idx = base + k;
        if (idx < Nc) { g_row[idx] = excl + v[k]; g_cur[idx] = 0; }
    }
    if (t == 0) g_row[Nc] = src[1023];
}

__global__ void csr_scatter(const int* __restrict__ ei)
{
    int e = blockIdx.x * blockDim.x + threadIdx.x;
    if (e >= EPc) return;
    int s, d;
    if (e < Ec) { s = ei[e]; d = ei[Ec + e]; } else { s = e - Ec; d = s; }
    int pos = atomicAdd(&g_cur[d], 1);
    g_esrc[g_row[d] + pos] = s;
}

// ---------------- GAT: node projection + attention logits --------------------
// Block = 16 nodes x 256 channels; thread t = channel t, node pairs packed in
// f32x2. One W LDG feeds 16 FMAs (kills the LDG-issue bottleneck).
template <int FIN>
__global__ void __launch_bounds__(HCc) gat_node_proj(
    const float* __restrict__ x, const float* __restrict__ W,
    const float* __restrict__ a_src, const float* __restrict__ a_dst)
{
    const int TM = 16, NP = TM / 2;
    int inst0 = blockIdx.x * TM;        // global instance = bt*Nc + node (16 | Nc)
    int t = threadIdx.x;                // channel
    int w = t >> 5, lane = t & 31;
    __shared__ float xsT[FIN][TM];      // transposed x tile (node pairs contiguous)
    __shared__ float wredS[TM][8], wredD[TM][8];

    for (int i = t; i < TM * FIN; i += HCc) {
        int n = i / FIN, k = i - n * FIN;
        xsT[k][n] = x[(size_t)(inst0 + n) * FIN + k];
    }
    __syncthreads();

    u64 acc[NP];
#pragma unroll
    for (int p = 0; p < NP; ++p) acc[p] = 0ull;
#pragma unroll 4
    for (int k = 0; k < FIN; ++k) {
        float wv = W[k * HCc + t];
        u64 w2 = pk2(wv, wv);
#pragma unroll
        for (int p = 0; p < NP; ++p) {
            u64 x2 = *(const u64*)&xsT[k][2 * p];
            fma2(acc[p], w2, x2);
        }
    }

    float asv = a_src[t], adv = a_dst[t];
#pragma unroll
    for (int p = 0; p < NP; ++p) {
        float lo, hi; upk2(lo, hi, acc[p]);
        g_hbuf[(size_t)(inst0 + 2 * p)     * HCc + t] = lo;
        g_hbuf[(size_t)(inst0 + 2 * p + 1) * HCc + t] = hi;
        float s0 = wsum(lo * asv), d0 = wsum(lo * adv);
        float s1 = wsum(hi * asv), d1 = wsum(hi * adv);
        if (lane == 0) {
            wredS[2 * p][w] = s0; wredD[2 * p][w] = d0;
            wredS[2 * p + 1][w] = s1; wredD[2 * p + 1][w] = d1;
        }
    }
    __syncthreads();
    if (t < TM * Hc) {                  // 64 threads: node n, head h
        int n = t >> 2, h = t & 3;
        int inst = inst0 + n;
        g_als[inst * Hc + h] = wredS[n][2 * h] + wredS[n][2 * h + 1];
        g_ald[inst * Hc + h] = wredD[n][2 * h] + wredD[n][2 * h + 1];
    }
}

// ---------------- GAT: atomic-free gather over incoming edges ----------------
__global__ void __launch_bounds__(64) gat_gather(const float* __restrict__ b,
                                                 float* __restrict__ out)
{
    int d  = blockIdx.x;
    int bt = blockIdx.y;
    int t  = threadIdx.x;               // 0..63
    int j  = t & 3;                     // head lane for logit work
    int head = t >> 4;                  // head for channel ownership
    int beg = g_row[d], deg = g_row[d + 1] - beg;
    float aldv = g_ald[(bt * Nc + d) * Hc + j];

    __shared__ float sm[8], sdenom[8], se[64], sacc[HCc];
    __shared__ int   ssrc[16];

    // pass A: max over incoming edges, per head
    float lm = -1e30f;
    for (int i0 = 0; i0 < deg; i0 += 16) {
        int i = i0 + (t >> 2);
        if (i < deg) {
            int s = g_esrc[beg + i];
            float v = g_als[(bt * Nc + s) * Hc + j] + aldv;
            v = v > 0.f ? v : 0.2f * v;
            lm = fmaxf(lm, v);
        }
    }
#pragma unroll
    for (int off = 4; off < 32; off <<= 1)
        lm = fmaxf(lm, __shfl_xor_sync(0xffffffffu, lm, off));
    if ((t & 31) < 4) sm[(t >> 5) * 4 + j] = lm;
    __syncthreads();
    float mh = fmaxf(sm[j], sm[4 + j]);

    // pass B: exp, denom, channel accumulate
    float dsum = 0.f;
    float4 acc = make_float4(0.f, 0.f, 0.f, 0.f);
    for (int c0 = 0; c0 < deg; c0 += 16) {
        int nim = min(16, deg - c0);
        if (t < nim) ssrc[t] = g_esrc[beg + c0 + t];
        __syncthreads();
        int i = t >> 2;
        if (i < nim) {
            int s = ssrc[i];
            float v = g_als[(bt * Nc + s) * Hc + j] + aldv;
            v = v > 0.f ? v : 0.2f * v;
            float e = __expf(v - mh);
            se[t] = e;
            dsum += e;
        }
        __syncthreads();
        for (int i2 = 0; i2 < nim; ++i2) {
            int s = ssrc[i2];
            float e = se[i2 * 4 + head];
            const float4 h4 = *(const float4*)(g_hbuf + ((size_t)(bt * Nc + s)) * HCc + t * 4);
            acc.x = fmaf(e, h4.x, acc.x);
            acc.y = fmaf(e, h4.y, acc.y);
            acc.z = fmaf(e, h4.z, acc.z);
            acc.w = fmaf(e, h4.w, acc.w);
        }
        __syncthreads();                 // before reusing ssrc/se
    }
#pragma unroll
    for (int off = 4; off < 32; off <<= 1)
        dsum += __shfl_xor_sync(0xffffffffu, dsum, off);
    if ((t & 31) < 4) sdenom[(t >> 5) * 4 + j] = dsum;
    __syncthreads();
    float invden = 1.f / (sdenom[head] + sdenom[4 + head]);
    sacc[4 * t + 0] = acc.x * invden;
    sacc[4 * t + 1] = acc.y * invden;
    sacc[4 * t + 2] = acc.z * invden;
    sacc[4 * t + 3] = acc.w * invden;
    __syncthreads();
    if (t < 16) {                        // 16 threads x 4 channels = 64 out channels
        float4 o;
        float* op = (float*)&o;
#pragma unroll
        for (int k = 0; k < 4; ++k) {
            int c = 4 * t + k;
            float sv = sacc[c] + sacc[Cc + c] + sacc[2 * Cc + c] + sacc[3 * Cc + c];
            op[k] = fmaxf(0.25f * sv + b[c], 0.f);
        }
        *(float4*)(out + ((size_t)(bt * Nc + d)) * Cc + 4 * t) = o;
    }
}

// ---------------- LSTM weight transpose: layout [k][u][gate] ------------------
__global__ void transpose_weights(const float* __restrict__ Wih, const float* __restrict__ Whh)
{
    int idx = blockIdx.x * blockDim.x + threadIdx.x;
    if (idx < Cc * HLc * 4) {
        int g = idx & 3, u = (idx >> 2) & (HLc - 1), k = idx >> 9;
        g_WihT[idx] = Wih[(g * HLc + u) * Cc + k];
    }
    if (idx < HLc * HLc * 4) {
        int g = idx & 3, u = (idx >> 2) & (HLc - 1), k = idx >> 9;
        g_WhhT[idx] = Whh[(g * HLc + u) * HLc + k];
    }
}

// ---------------- fused LSTM (all 8 steps, f32x2) + fusion head ---------------
// Block = 16 batch elements (8 f32x2 pairs), 128 threads (thread u = unit u).
__global__ void __launch_bounds__(HLc) lstm_head(
    const float* __restrict__ b_ih, const float* __restrict__ b_hh,
    const float* __restrict__ Wf,   const float* __restrict__ bfv,
    const float* __restrict__ Wo,   const float* __restrict__ bov,
    float* __restrict__ out)
{
    const int TB = 16, NP = TB / 2;
    int u   = threadIdx.x;
    int gb0 = blockIdx.x * TB;          // gb = b*Nc + n; 16 | Nc so b constant per block
    int b   = gb0 / Nc;
    int n0  = gb0 - b * Nc;
    __shared__ float xs2[NP][Cc][2];    // pair-packed inputs
    __shared__ float hs2[NP][HLc][2];   // pair-packed hidden state
    __shared__ float red[TB][HLc];
    float creg[TB];
#pragma unroll
    for (int bb = 0; bb < TB; ++bb) creg[bb] = 0.f;
#pragma unroll
    for (int p = 0; p < NP; ++p) { hs2[p][u][0] = 0.f; hs2[p][u][1] = 0.f; }

    float bi  = b_ih[u]           + b_hh[u];
    float bff = b_ih[HLc + u]     + b_hh[HLc + u];
    float bg  = b_ih[2 * HLc + u] + b_hh[2 * HLc + u];
    float bo  = b_ih[3 * HLc + u] + b_hh[3 * HLc + u];
    u64 bi2 = pk2(bi, bi), bf2 = pk2(bff, bff), bg2 = pk2(bg, bg), bo2 = pk2(bo, bo);

    for (int t = 0; t < Tc; ++t) {
        const float* gsrc = g_g2 + ((size_t)(b * Tc + t) * Nc + n0) * Cc;
        __syncthreads();                // hs2 writes of prev step + xs2 reuse
        for (int i = u; i < TB * Cc; i += HLc) {
            int n = i >> 6, k = i & (Cc - 1);
            xs2[n >> 1][k][n & 1] = gsrc[i];
        }
        __syncthreads();

        u64 ai[NP], af[NP], ag[NP], ao[NP];
#pragma unroll
        for (int p = 0; p < NP; ++p) { ai[p] = bi2; af[p] = bf2; ag[p] = bg2; ao[p] = bo2; }

#pragma unroll 2
        for (int k = 0; k < Cc; ++k) {
            float4 w4 = *(const float4*)&g_WihT[(k * HLc + u) * 4];
            u64 wi = pk2(w4.x, w4.x), wf = pk2(w4.y, w4.y);
            u64 wg = pk2(w4.z, w4.z), wo = pk2(w4.w, w4.w);
#pragma unroll
            for (int p = 0; p < NP; ++p) {
                u64 x2 = *(const u64*)&xs2[p][k][0];
                fma2(ai[p], wi, x2);
                fma2(af[p], wf, x2);
                fma2(ag[p], wg, x2);
                fma2(ao[p], wo, x2);
            }
        }
#pragma unroll 2
        for (int k = 0; k < HLc; ++k) {
            float4 w4 = *(const float4*)&g_WhhT[(k * HLc + u) * 4];
            u64 wi = pk2(w4.x, w4.x), wf = pk2(w4.y, w4.y);
            u64 wg = pk2(w4.z, w4.z), wo = pk2(w4.w, w4.w);
#pragma unroll
            for (int p = 0; p < NP; ++p) {
                u64 h2 = *(const u64*)&hs2[p][k][0];
                fma2(ai[p], wi, h2);
                fma2(af[p], wf, h2);
                fma2(ag[p], wg, h2);
                fma2(ao[p], wo, h2);
            }
        }
        __syncthreads();                 // all hs2 reads done before overwrite
#pragma unroll
        for (int p = 0; p < NP; ++p) {
            float il, ih, fl, fh, gl, gh, ol, oh;
            upk2(il, ih, ai[p]); upk2(fl, fh, af[p]);
            upk2(gl, gh, ag[p]); upk2(ol, oh, ao[p]);
            float cv0 = fsig(fl) * creg[2 * p]     + fsig(il) * ftanh(gl);
            float cv1 = fsig(fh) * creg[2 * p + 1] + fsig(ih) * ftanh(gh);
            creg[2 * p]     = cv0;
            creg[2 * p + 1] = cv1;
            hs2[p][u][0] = fsig(ol) * ftanh(cv0);
            hs2[p][u][1] = fsig(oh) * ftanh(cv1);
        }
    }
    __syncthreads();
    // fusion head: xs2 still holds t=T-1 (= g_last); hs2 holds h_T
#pragma unroll 1
    for (int bb = 0; bb < TB; ++bb) {
        int p = bb >> 1, par = bb & 1;
        float f = bfv[u];
        for (int k = 0; k < HLc; ++k) f = fmaf(hs2[p][k][par], Wf[k * FHc + u], f);
        for (int k = 0; k < Cc;  ++k) f = fmaf(xs2[p][k][par], Wf[(HLc + k) * FHc + u], f);
        f = fmaxf(f, 0.f);
        red[bb][u] = f * Wo[u];
    }
    __syncthreads();
    if (u < TB) {
        float s = bov[0];
        for (int k = 0; k < HLc; ++k) s += red[u][k];
        out[gb0 + u] = s;
    }
}

// ---------------- launch ------------------------------------------------------
extern "C" void kernel_launch(void* const* d_in, const int* in_sizes, int n_in,
                              void* d_out, int out_size)
{
    const float* x_seq  = (const float*)d_in[0];
    const float* W1     = (const float*)d_in[1];
    const float* a_src1 = (const float*)d_in[2];
    const float* a_dst1 = (const float*)d_in[3];
    const float* b1     = (const float*)d_in[4];
    const float* W2     = (const float*)d_in[5];
    const float* a_src2 = (const float*)d_in[6];
    const float* a_dst2 = (const float*)d_in[7];
    const float* b2     = (const float*)d_in[8];
    const float* W_ih   = (const float*)d_in[9];
    const float* W_hh   = (const float*)d_in[10];
    const float* b_ih   = (const float*)d_in[11];
    const float* b_hh   = (const float*)d_in[12];
    const float* Wf     = (const float*)d_in[13];
    const float* bf     = (const float*)d_in[14];
    const float* Wo     = (const float*)d_in[15];
    const float* bo     = (const float*)d_in[16];
    const int*   ei     = (const int*)d_in[17];
    float* out = (float*)d_out;

    float* g1p; cudaGetSymbolAddress((void**)&g1p, g_g1);
    float* g2p; cudaGetSymbolAddress((void**)&g2p, g_g2);

    dim3 ggrid(Nc, BTc);
    const int projBlocks = BTc * Nc / 16;   // 4000

    // CSR build (graph shared across all BT instances)
    csr_zero<<<(Nc + 255) / 256, 256>>>();
    csr_count<<<(EPc + 255) / 256, 256>>>(ei);
    csr_scan<<<1, 1024>>>();
    csr_scatter<<<(EPc + 255) / 256, 256>>>(ei);

    // Layer 1
    gat_node_proj<FIN0><<<projBlocks, HCc>>>(x_seq, W1, a_src1, a_dst1);
    gat_gather<<<ggrid, 64>>>(b1, g1p);

    // Layer 2 (input = g1)
    gat_node_proj<Cc><<<projBlocks, HCc>>>(g1p, W2, a_src2, a_dst2);
    gat_gather<<<ggrid, 64>>>(b2, g2p);

    // LSTM + head
    transpose_weights<<<(HLc * HLc * 4 + 255) / 256, 256>>>(W_ih, W_hh);
    lstm_head<<<(Bc * Nc) / 16, HLc>>>(b_ih, b_hh, Wf, bf, Wo, bo, out);
}